// round 9
// baseline (speedup 1.0000x reference)
#include <cuda_runtime.h>
#include <cstdint>

// Problem constants (fixed by setup_inputs)
#define N      2048
#define DMDIM  128
#define KDIAG  (2*N - 1)           // 4095 anti-diagonals
#define DIAG_ELEMS (KDIAG * N)     // 8,386,560
#define BIGF   1e10f
#define GAMMA_ 0.1f
#define INVG   10.0f               // 1/GAMMA
#define MARGINF 2.0f

#define CSPLIT 32                  // CTAs per matrix in the wavefront
#define BCOLS  64                  // columns per CTA (2 per lane)

// Static scratch only (no runtime allocation allowed)
__device__ float  g_D[3][DIAG_ELEMS];        // diag-major: D[z][(i+j)*N + i]
__device__ float  g_norms[2][N];
__device__ float  g_dtw[3];
__device__ double g_part[512];
__device__ float4 g_bnd[3][CSPLIT][KDIAG];   // {r1, r2, tag=step, pad}

// ---------------------------------------------------------------------------
// Kernel A: clear boundary tags (must precede softdtw each launch/replay)
// ---------------------------------------------------------------------------
__global__ void clear_bnd_kernel() {
    const int n = 3 * CSPLIT * KDIAG;
    float4* p = &g_bnd[0][0][0];
    float4 z = make_float4(0.f, 0.f, 0.f, 0.f);
    for (int i = blockIdx.x * blockDim.x + threadIdx.x; i < n;
         i += gridDim.x * blockDim.x)
        p[i] = z;
}

// ---------------------------------------------------------------------------
// Kernel 0: row squared norms for x and y
// ---------------------------------------------------------------------------
__global__ void norm_kernel(const float* __restrict__ x,
                            const float* __restrict__ y) {
    int r = blockIdx.x * blockDim.x + threadIdx.x;   // 0..2N-1
    if (r >= 2 * N) return;
    const float* p = (r < N) ? (x + (size_t)r * DMDIM)
                             : (y + (size_t)(r - N) * DMDIM);
    const float4* p4 = (const float4*)p;
    float s = 0.0f;
#pragma unroll
    for (int k = 0; k < DMDIM / 4; k++) {
        float4 v = p4[k];
        s += v.x * v.x + v.y * v.y + v.z * v.z + v.w * v.w;
    }
    g_norms[r < N ? 0 : 1][r < N ? r : r - N] = s;
}

// ---------------------------------------------------------------------------
// Kernel 1: pairwise sqdist -> diag-major (smem-staged, coalesced writeout),
// fused contrastive-IDM reduction for z=1 (x,x) and z=2 (y,y).
// ---------------------------------------------------------------------------
#define TILE 128
#define KC   16
#define DS_STRIDE 130    // pad: diagonal reads conflict-free

extern __shared__ float sdyn[];  // Ds[128][130] = 66560 B (dynamic smem)

__global__ __launch_bounds__(256)
void pairdist_kernel(const float* __restrict__ x,
                     const float* __restrict__ y,
                     const float* __restrict__ aidx,
                     const float* __restrict__ bidx,
                     float thr) {
    int z = blockIdx.z;
    const float* A  = (z == 2) ? y : x;
    const float* B  = (z == 1) ? x : y;
    const float* nA = (z == 2) ? g_norms[1] : g_norms[0];
    const float* nB = (z == 1) ? g_norms[0] : g_norms[1];
    const float* gidx = (z == 1) ? aidx : bidx;

    int bi = blockIdx.y, bj = blockIdx.x;
    __shared__ float As[TILE][KC + 1];
    __shared__ float Bs[TILE][KC + 1];
    __shared__ double sh[256];

    int t  = threadIdx.x;
    int tx = t & 15, ty = t >> 4;

    float acc[8][8];
#pragma unroll
    for (int u = 0; u < 8; u++)
#pragma unroll
        for (int v = 0; v < 8; v++) acc[u][v] = 0.0f;

    for (int kb = 0; kb < DMDIM; kb += KC) {
        for (int idx = t; idx < TILE * KC; idx += 256) {
            int rr = idx >> 4, kk = idx & 15;
            As[rr][kk] = A[(size_t)(bi * TILE + rr) * DMDIM + kb + kk];
            Bs[rr][kk] = B[(size_t)(bj * TILE + rr) * DMDIM + kb + kk];
        }
        __syncthreads();
#pragma unroll
        for (int kk = 0; kk < KC; kk++) {
            float a[8], b[8];
#pragma unroll
            for (int u = 0; u < 8; u++) a[u] = As[ty + 16 * u][kk];
#pragma unroll
            for (int v = 0; v < 8; v++) b[v] = Bs[tx + 16 * v][kk];
#pragma unroll
            for (int u = 0; u < 8; u++)
#pragma unroll
                for (int v = 0; v < 8; v++) acc[u][v] += a[u] * b[v];
        }
        __syncthreads();
    }

    // epilogue: d into smem tile + fused idm
    float gxu[8], gxv[8], nau[8], nbv[8];
#pragma unroll
    for (int u = 0; u < 8; u++) {
        int gi = bi * TILE + ty + 16 * u;
        nau[u] = nA[gi];
        gxu[u] = (z != 0) ? gidx[gi] : 0.0f;
    }
#pragma unroll
    for (int v = 0; v < 8; v++) {
        int gj = bj * TILE + tx + 16 * v;
        nbv[v] = nB[gj];
        gxv[v] = (z != 0) ? gidx[gj] : 0.0f;
    }

    float idm_acc = 0.0f;
#pragma unroll
    for (int u = 0; u < 8; u++) {
        int li = ty + 16 * u;
#pragma unroll
        for (int v = 0; v < 8; v++) {
            int lj = tx + 16 * v;
            float d = fmaxf(nau[u] + nbv[v] - 2.0f * acc[u][v], 0.0f);
            sdyn[li * DS_STRIDE + lj] = d;
            if (z != 0) {
                float gd   = gxu[u] - gxv[v];
                float prob = fmaxf(MARGINF - d, 0.0f);
                idm_acc += ((fabsf(gd) - thr) > 0.0f)
                             ? (1.0f + gd * gd) * prob : d;
            }
        }
    }
    __syncthreads();

    // coalesced diag-major writeout: 255 tile-diagonals, 2 per iteration
    float* Dz = g_D[z];
    int kbase = (bi + bj) * TILE;
    int half  = t >> 7;           // 0 or 1
    int tt    = t & 127;
    for (int kp = 0; kp < 255; kp += 2) {
        int k1 = kp + half;
        if (k1 < 255) {
            int ilo = max(0, k1 - 127), ihi = min(127, k1);
            int i = ilo + tt;
            if (i <= ihi)
                Dz[(size_t)(kbase + k1) * N + bi * TILE + i] =
                    sdyn[i * DS_STRIDE + (k1 - i)];
        }
    }

    if (z != 0) {
        sh[t] = (double)idm_acc;
        __syncthreads();
        for (int off = 128; off > 0; off >>= 1) {
            if (t < off) sh[t] += sh[t + off];
            __syncthreads();
        }
        if (t == 0)
            g_part[(z - 1) * 256 + bi * 16 + bj] = sh[0];
    }
}

// ---------------------------------------------------------------------------
// softmin cell:  out = d + softmin(left, up, diag)
// Exact skip: both margins <= -2 => e1+e2 < 2^-24 => 1+e1+e2 == 1.0f exactly.
// ---------------------------------------------------------------------------
__device__ __forceinline__ float cellf(float d, float left, float up,
                                       float dg, bool valid) {
    float lo = fminf(dg, up), hi = fmaxf(dg, up);
    float mm = fminf(lo, left);
    float o1 = fmaxf(lo, left);
    float o2 = hi;
    float m1 = mm - o1, m2 = mm - o2;        // both <= 0
    float smin;
    if (fmaxf(m1, m2) > -2.0f) {
        float e1 = __expf(m1 * INVG);
        float e2 = __expf(m2 * INVG);
        smin = mm - GAMMA_ * __logf(1.0f + e1 + e2);
    } else {
        smin = mm;
    }
    return valid ? (d + smin) : BIGF;
}

// volatile 16B boundary record ops (single-transaction, L1-bypassing)
__device__ __forceinline__ void bnd_write(float4* p, float a, float b, int k) {
    asm volatile("st.volatile.global.v4.f32 [%0], {%1,%2,%3,%4};" ::
        "l"(p), "f"(a), "f"(b), "f"(__int_as_float(k)), "f"(0.0f) : "memory");
}
__device__ __forceinline__ float4 bnd_read(const float4* p) {
    float4 v;
    asm volatile("ld.volatile.global.v4.f32 {%0,%1,%2,%3}, [%4];" :
        "=f"(v.x), "=f"(v.y), "=f"(v.z), "=f"(v.w) : "l"(p));
    return v;
}

// ---------------------------------------------------------------------------
// Kernel 2: decoupled multi-CTA soft-DTW wavefront.
// 3 matrices x CSPLIT one-warp CTAs; 2 columns per lane; no __syncthreads.
// Cross-CTA boundaries via tagged volatile records, prefetched 8 steps ahead;
// D rows prefetched in a depth-8 register ring.
// ---------------------------------------------------------------------------
__global__ __launch_bounds__(32)
void softdtw_kernel() {
    int bid  = blockIdx.x;
    int m    = bid >> 5;          // matrix
    int c    = bid & 31;          // column block
    int lane = threadIdx.x;
    const float* base = g_D[m];
    int col0 = c * BCOLS + lane * 2;

    const int k_lo = c * BCOLS;
    const int k_hi = c * BCOLS + BCOLS - 1 + N - 1;   // last step with a valid col

    float r1x = BIGF, r1y = BIGF, r2x = BIGF, r2y = BIGF;
    if (c == 0 && lane == 0) r1x = base[0];

    // first real step, aligned so ks == 1 (mod 8) for static ring slots
    int k_start = (k_lo > 1) ? k_lo : 1;
    int ks = ((k_start - 1) & ~7) + 1;

    float2 ring[8];               // D rows k .. k+7
    float4 bring[8];              // boundary records k-1 .. k+6 (lane 0)
    const bool has_left = (c > 0);
#pragma unroll
    for (int q = 0; q < 8; q++) {
        int rk = ks + q;
        if (rk <= k_hi)
            ring[q] = *(const float2*)(base + (size_t)rk * N + col0);
        if (lane == 0 && has_left)
            bring[q] = bnd_read(&g_bnd[m][c - 1][min(rk - 1, KDIAG - 1)]);
    }

    const bool is_last = (c == CSPLIT - 1) && (lane == 31);

    for (int kk = ks; kk < KDIAG && kk <= k_hi; kk += 8) {
#pragma unroll
        for (int u = 0; u < 8; u++) {
            int k = kk + u;
            float2 d = ring[u];
            int nk = k + 8;
            if (nk <= k_hi)
                ring[u] = *(const float2*)(base + (size_t)nk * N + col0);

            float n1 = __shfl_up_sync(0xffffffffu, r1y, 1);
            float n2 = __shfl_up_sync(0xffffffffu, r2y, 1);

            bool v0 = (col0 <= k)     & ((k - col0) < N);
            bool v1 = (col0 + 1 <= k) & ((k - col0 - 1) < N);

            if (lane == 0) {
                if (has_left && v0) {
                    int want = k - 1;
                    float4 v = bring[u];
                    if (__float_as_int(v.z) != want) {
                        const float4* p = &g_bnd[m][c - 1][want];
                        do { v = bnd_read(p); }
                        while (__float_as_int(v.z) != want);
                    }
                    n1 = v.x; n2 = v.y;
                } else {
                    n1 = BIGF; n2 = BIGF;
                }
                if (has_left)   // prefetch record (k+7) for step k+8
                    bring[u] = bnd_read(&g_bnd[m][c - 1][min(k + 7, KDIAG - 1)]);
            }

            float o0 = cellf(d.x, r1x, n1,  n2,  v0);
            float o1 = cellf(d.y, r1y, r1x, r2x, v1);
            r2x = r1x; r1x = o0;
            r2y = r1y; r1y = o1;

            if (lane == 31 && v1)
                bnd_write(&g_bnd[m][c][k], r1y, r2y, k);

            // capture final cell (i=2047, k=4094) BEFORE trailing invalid
            // steps in this octet overwrite r1y with BIGF
            if (is_last && k == KDIAG - 1)
                g_dtw[m] = o1;
        }
    }
}

// ---------------------------------------------------------------------------
// Kernel 3: combine -> scalar output
// ---------------------------------------------------------------------------
__global__ __launch_bounds__(256)
void combine_kernel(float* __restrict__ out) {
    __shared__ double sh[256];
    double s = 0.0;
    for (int i = threadIdx.x; i < 512; i += 256) s += g_part[i];
    sh[threadIdx.x] = s;
    __syncthreads();
    for (int off = 128; off > 0; off >>= 1) {
        if (threadIdx.x < off) sh[threadIdx.x] += sh[threadIdx.x + off];
        __syncthreads();
    }
    if (threadIdx.x == 0) {
        double pos = (double)g_dtw[0] - 0.5 * ((double)g_dtw[1] + (double)g_dtw[2]);
        out[0] = (float)((pos + sh[0]) * (1.0 / 2048.0));   // / NUM_FRAMES
    }
}

// ---------------------------------------------------------------------------
extern "C" void kernel_launch(void* const* d_in, const int* in_sizes, int n_in,
                              void* d_out, int out_size) {
    const float* a_emb = (const float*)d_in[0];
    const float* b_emb = (const float*)d_in[1];
    const float* a_idx = (const float*)d_in[2];
    const float* b_idx = (const float*)d_in[3];
    int n = in_sizes[2];                       // 2048
    float thr = 10.0f / (float)n;              // SIGMA / seq_len (exact dyadic)

    // Unconditional, deterministic, idempotent; not a stream op (capture-safe).
    cudaFuncSetAttribute(pairdist_kernel,
                         cudaFuncAttributeMaxDynamicSharedMemorySize,
                         TILE * DS_STRIDE * (int)sizeof(float));

    clear_bnd_kernel<<<256, 256>>>();
    norm_kernel<<<(2 * N + 255) / 256, 256>>>(a_emb, b_emb);

    dim3 pg(N / TILE, N / TILE, 3);
    pairdist_kernel<<<pg, 256, TILE * DS_STRIDE * sizeof(float)>>>(
        a_emb, b_emb, a_idx, b_idx, thr);

    softdtw_kernel<<<3 * CSPLIT, 32>>>();

    combine_kernel<<<1, 256>>>((float*)d_out);
}